// round 6
// baseline (speedup 1.0000x reference)
#include <cuda_runtime.h>
#include <cuda_bf16.h>
#include <math.h>

typedef unsigned long long ull;

#define NBLK 128
#define NSTEP 50
#define LDP_OUT 50304   // 393*128, padded ld for partials
#define NOUT 50257

// ---------------- device scratch (no allocs allowed) ----------------
__device__ float g_X[64 * 1024];          // padded inputs (rows 50..63 zero)
__device__ float g_Gin[50 * 4096];        // W_ih @ x_t + b_ih + b_hh
__device__ float g_HS[64 * 1024];         // h_t history (rows 50..63 zero)
__device__ __align__(16) ull g_htag[2][1024];  // (tag<<32)|h_bits, double-buffered
__device__ float g_P[2 * 64 * LDP_OUT];   // split-K partial buffers (reused)

// ---------------- helpers ----------------
__device__ __forceinline__ ull pack2(float x, float y) {
    ull r;
    asm("mov.b64 %0, {%1, %2};" : "=l"(r) : "f"(x), "f"(y));
    return r;
}
__device__ __forceinline__ void ffma2(ull& d, ull a, ull b) {
    asm("fma.rn.f32x2 %0, %1, %2, %0;" : "+l"(d) : "l"(a), "l"(b));
}
__device__ __forceinline__ float sum2(ull a) {
    float2 v = *(float2*)&a;
    return v.x + v.y;
}
// morally-strong relaxed gpu-scope 64-bit ops: per-word atomic, no tearing
__device__ __forceinline__ void st_relaxed_u64(ull* p, ull v) {
    asm volatile("st.relaxed.gpu.global.u64 [%0], %1;" :: "l"(p), "l"(v) : "memory");
}
__device__ __forceinline__ ull ld_relaxed_u64(const ull* p) {
    ull v;
    asm volatile("ld.relaxed.gpu.global.u64 %0, [%1];" : "=l"(v) : "l"(p) : "memory");
    return v;
}

// ---------------- prep: gather X rows, zero pads, init tagged h0 ----------------
__global__ void prep_kernel(const int* __restrict__ sent,
                            const float* __restrict__ emb,
                            const float* __restrict__ h0) {
    int b = blockIdx.x;
    int tid = threadIdx.x;  // 256 threads
    if (b < 64) {
        float4* dst = (float4*)(g_X + b * 1024);
        if (b < 50) {
            int row = (b == 0) ? 1 : sent[b - 1];  // START_ID = 1
            const float4* src = (const float4*)(emb + (size_t)row * 1024);
            dst[tid] = src[tid];
        } else {
            float4 z = make_float4(0.f, 0.f, 0.f, 0.f);
            dst[tid] = z;
            ((float4*)(g_HS + b * 1024))[tid] = z;  // keep GEMM pad rows zero
        }
    } else {
        // parity0 <- h0 with tag 1; parity1 <- tag 0 (clear stale tags)
        float4 h4 = ((const float4*)h0)[tid];
        int i = tid * 4;
        st_relaxed_u64(&g_htag[0][i + 0], (1ull << 32) | (ull)__float_as_uint(h4.x));
        st_relaxed_u64(&g_htag[0][i + 1], (1ull << 32) | (ull)__float_as_uint(h4.y));
        st_relaxed_u64(&g_htag[0][i + 2], (1ull << 32) | (ull)__float_as_uint(h4.z));
        st_relaxed_u64(&g_htag[0][i + 3], (1ull << 32) | (ull)__float_as_uint(h4.w));
        st_relaxed_u64(&g_htag[1][i + 0], 0ull);
        st_relaxed_u64(&g_htag[1][i + 1], 0ull);
        st_relaxed_u64(&g_htag[1][i + 2], 0ull);
        st_relaxed_u64(&g_htag[1][i + 3], 0ull);
    }
}

// ---------------- split-K GEMM: P[ks][m][n] = A[m][kbeg:kend] . W[n][kbeg:kend] ----------------
// A: [64][K] row-major. W: [N][K] row-major. P: [nsplit][64][ldp].
// BM=64, BN=128, BK=16, 128 threads, 8x8 thread tiles, f32x2, smem double-buffered.
__global__ __launch_bounds__(128) void gemm_splitk(
    const float* __restrict__ A, const float* __restrict__ W,
    float* __restrict__ P, int N, int K, int ldp, int nsplit) {
    __shared__ ull sAd[2][16][64];     // A duplicated as (a,a) pairs
    __shared__ float sB[2][16][128];

    const int tid = threadIdx.x;
    const int tn = tid & 15;   // n0 = tn*8
    const int tm = tid >> 4;   // m0 = tm*8
    const int n_block = blockIdx.x * 128;
    const int klen = K / nsplit;
    const int kbeg = blockIdx.y * klen;
    const int nk = klen / 16;
    float* Pp = P + (size_t)blockIdx.y * 64 * ldp;

    ull acc[8][4];
#pragma unroll
    for (int i = 0; i < 8; i++)
#pragma unroll
        for (int p = 0; p < 4; p++) acc[i][p] = 0ULL;

    const int mA = tid & 63;
    const int kgA = tid >> 6;          // 0..1 (with s offset -> 0..3)
    const int nB = tid & 127;

    float4 ra[2], rb[4];
    // prologue: load tile 0
#pragma unroll
    for (int s = 0; s < 2; s++) {
        int kg = kgA + s * 2;
        ra[s] = *(const float4*)(A + (size_t)mA * K + kbeg + kg * 4);
    }
#pragma unroll
    for (int s = 0; s < 4; s++) {
        int gn = n_block + nB;
        rb[s] = make_float4(0.f, 0.f, 0.f, 0.f);
        if (gn < N) rb[s] = *(const float4*)(W + (size_t)gn * K + kbeg + s * 4);
    }
    {
#pragma unroll
        for (int s = 0; s < 2; s++) {
            int kg = kgA + s * 2;
            sAd[0][kg * 4 + 0][mA] = pack2(ra[s].x, ra[s].x);
            sAd[0][kg * 4 + 1][mA] = pack2(ra[s].y, ra[s].y);
            sAd[0][kg * 4 + 2][mA] = pack2(ra[s].z, ra[s].z);
            sAd[0][kg * 4 + 3][mA] = pack2(ra[s].w, ra[s].w);
        }
#pragma unroll
        for (int s = 0; s < 4; s++) {
            sB[0][s * 4 + 0][nB] = rb[s].x;
            sB[0][s * 4 + 1][nB] = rb[s].y;
            sB[0][s * 4 + 2][nB] = rb[s].z;
            sB[0][s * 4 + 3][nB] = rb[s].w;
        }
    }
    __syncthreads();

    for (int kt = 0; kt < nk; kt++) {
        const int buf = kt & 1;
        if (kt + 1 < nk) {
            int kp = kbeg + (kt + 1) * 16;
#pragma unroll
            for (int s = 0; s < 2; s++) {
                int kg = kgA + s * 2;
                ra[s] = *(const float4*)(A + (size_t)mA * K + kp + kg * 4);
            }
#pragma unroll
            for (int s = 0; s < 4; s++) {
                int gn = n_block + nB;
                rb[s] = make_float4(0.f, 0.f, 0.f, 0.f);
                if (gn < N) rb[s] = *(const float4*)(W + (size_t)gn * K + kp + s * 4);
            }
        }
#pragma unroll
        for (int k = 0; k < 16; k++) {
            const ull* ap = &sAd[buf][k][tm * 8];
            const ull* bp = (const ull*)&sB[buf][k][tn * 8];
            ull b0 = bp[0], b1 = bp[1], b2 = bp[2], b3 = bp[3];
#pragma unroll
            for (int i = 0; i < 8; i++) {
                ull ai = ap[i];
                ffma2(acc[i][0], ai, b0);
                ffma2(acc[i][1], ai, b1);
                ffma2(acc[i][2], ai, b2);
                ffma2(acc[i][3], ai, b3);
            }
        }
        if (kt + 1 < nk) {
            const int nb = buf ^ 1;
#pragma unroll
            for (int s = 0; s < 2; s++) {
                int kg = kgA + s * 2;
                sAd[nb][kg * 4 + 0][mA] = pack2(ra[s].x, ra[s].x);
                sAd[nb][kg * 4 + 1][mA] = pack2(ra[s].y, ra[s].y);
                sAd[nb][kg * 4 + 2][mA] = pack2(ra[s].z, ra[s].z);
                sAd[nb][kg * 4 + 3][mA] = pack2(ra[s].w, ra[s].w);
            }
#pragma unroll
            for (int s = 0; s < 4; s++) {
                sB[nb][s * 4 + 0][nB] = rb[s].x;
                sB[nb][s * 4 + 1][nB] = rb[s].y;
                sB[nb][s * 4 + 2][nB] = rb[s].z;
                sB[nb][s * 4 + 3][nB] = rb[s].w;
            }
            __syncthreads();
        }
    }

    // epilogue: only valid rows (m<50) — pad rows are never read by combine
#pragma unroll
    for (int i = 0; i < 8; i++) {
        int m = tm * 8 + i;
        if (m < 50) {
            float4* dst = (float4*)(Pp + (size_t)m * ldp + n_block + tn * 8);
            dst[0] = *(float4*)&acc[i][0];
            dst[1] = *(float4*)&acc[i][2];
        }
    }
}

// ---------------- combine: out = P0 + P1 + bias ----------------
__global__ void combine_out_kernel(const float* __restrict__ bout,
                                   float* __restrict__ out) {
    int m = blockIdx.y;
    int n = blockIdx.x * 256 + threadIdx.x;
    if (n < NOUT) {
        size_t po = (size_t)m * LDP_OUT + n;
        out[(size_t)m * NOUT + n] = g_P[po] + g_P[(size_t)64 * LDP_OUT + po] + bout[n];
    }
}

// ---------------- combine: Gin = P0+P1+P2+P3 + bih + bhh ----------------
__global__ void combine_gin_kernel(const float* __restrict__ bih,
                                   const float* __restrict__ bhh) {
    int m = blockIdx.y;
    int n = blockIdx.x * 256 + threadIdx.x;
    float s = bih[n] + bhh[n];
#pragma unroll
    for (int sp = 0; sp < 4; sp++) s += g_P[(size_t)sp * 64 * 4096 + (size_t)m * 4096 + n];
    g_Gin[(size_t)m * 4096 + n] = s;
}

// ---------------- persistent LSTM recurrence (warp-per-unit, tag-polled) ----------------
// 128 blocks x 256 threads (1/SM). Warp w of block b owns hidden unit u=b*8+w:
// all 4 gate rows. lane = r*8+c (r=gate 0..3, c=chunk 0..7).
// After the 8-lane chunk reduce, the 4 gate sums live in the same warp; lane 0
// applies the nonlinearity (cell state in a register) and publishes its tagged
// h word immediately. No block-wide sync on the tail.
__global__ __launch_bounds__(256, 1) void lstm_persistent(
    const float* __restrict__ Whh,      // [4096][1024]
    const float* __restrict__ gin_all,  // [50][4096]
    const float* __restrict__ c0) {     // [1024]
    const int b = blockIdx.x;
    const int tid = threadIdx.x;
    const int w = tid >> 5;              // warp -> unit b*8+w
    const int lane = tid & 31;
    const int r = lane >> 3;             // gate 0..3
    const int c = lane & 7;              // chunk 0..7
    const int u = b * 8 + w;
    const int grow = r * 1024 + u;       // W_hh row for this lane

    __shared__ __align__(16) ull h_q[512];  // h packed as (h2i, h2i+1) pairs
    __shared__ float sGin[NSTEP][4][8];     // this block's Gin slice, all steps

    // preload Gin slice: 200 segments of 8 floats
    if (tid < 200) {
        int t = tid >> 2, g = tid & 3;
        const float4* src = (const float4*)(gin_all + (size_t)t * 4096 + g * 1024 + b * 8);
        ((float4*)&sGin[t][g][0])[0] = src[0];
        ((float4*)&sGin[t][g][0])[1] = src[1];
    }
    float cc = 0.f;
    if (lane == 0) cc = c0[u];

    // W_hh slice into registers, pre-packed as f32x2 pairs
    ull Wq[64];
    const float4* wp = (const float4*)(Whh + (size_t)grow * 1024);
#pragma unroll
    for (int it = 0; it < 32; it++) {
        float4 w4 = wp[it * 8 + c];
        Wq[2 * it + 0] = pack2(w4.x, w4.y);
        Wq[2 * it + 1] = pack2(w4.z, w4.w);
    }
    __syncthreads();

    for (int t = 0; t < NSTEP; t++) {
        // poll-stage h: thread tid owns units 4*tid .. 4*tid+3
        {
            const ull* p = &g_htag[t & 1][tid * 4];
            const unsigned expt = (unsigned)(t + 1);
            ull x0, x1, x2, x3;
            for (;;) {
                x0 = ld_relaxed_u64(p + 0);
                x1 = ld_relaxed_u64(p + 1);
                x2 = ld_relaxed_u64(p + 2);
                x3 = ld_relaxed_u64(p + 3);
                if ((unsigned)(x0 >> 32) == expt && (unsigned)(x1 >> 32) == expt &&
                    (unsigned)(x2 >> 32) == expt && (unsigned)(x3 >> 32) == expt)
                    break;
            }
            ulonglong2 hq;
            hq.x = pack2(__uint_as_float((unsigned)x0), __uint_as_float((unsigned)x1));
            hq.y = pack2(__uint_as_float((unsigned)x2), __uint_as_float((unsigned)x3));
            *((ulonglong2*)&h_q[2 * tid]) = hq;
        }
        __syncthreads();  // h_q complete for all warps

        ull a0 = 0, a1 = 0;
#pragma unroll
        for (int it = 0; it < 32; it++) {
            ulonglong2 hq = *(const ulonglong2*)&h_q[it * 16 + c * 2];  // 4-way bcast, conflict-free
            ffma2(a0, Wq[2 * it + 0], hq.x);
            ffma2(a1, Wq[2 * it + 1], hq.y);
        }
        float sum = sum2(a0) + sum2(a1);
        // reduce over the 8 chunk lanes (stays within each gate's lane group)
        sum += __shfl_xor_sync(0xFFFFFFFFu, sum, 1);
        sum += __shfl_xor_sync(0xFFFFFFFFu, sum, 2);
        sum += __shfl_xor_sync(0xFFFFFFFFu, sum, 4);
        sum += sGin[t][r][w];  // add precomputed input-projection + biases

        // gather the 4 gate values to lane 0
        float vi = __shfl_sync(0xFFFFFFFFu, sum, 0);
        float vf = __shfl_sync(0xFFFFFFFFu, sum, 8);
        float vg = __shfl_sync(0xFFFFFFFFu, sum, 16);
        float vo = __shfl_sync(0xFFFFFFFFu, sum, 24);

        if (lane == 0) {
            float ig = __fdividef(1.f, 1.f + __expf(-vi));
            float fg = __fdividef(1.f, 1.f + __expf(-vf));
            float gg = 1.f - __fdividef(2.f, __expf(2.f * vg) + 1.f);
            float og = __fdividef(1.f, 1.f + __expf(-vo));
            float cn = fg * cc + ig * gg;
            cc = cn;
            float hn = og * (1.f - __fdividef(2.f, __expf(2.f * cn) + 1.f));
            // publish: value+tag in one morally-strong 64-bit word
            ull v = ((ull)(unsigned)(t + 2) << 32) | (ull)__float_as_uint(hn);
            st_relaxed_u64(&g_htag[(t + 1) & 1][u], v);
            g_HS[(size_t)t * 1024 + u] = hn;
        }
        // no trailing barrier: next step's poll enforces ordering
    }
}

// ---------------- launch ----------------
extern "C" void kernel_launch(void* const* d_in, const int* in_sizes, int n_in,
                              void* d_out, int out_size) {
    const int* sent = (const int*)d_in[0];
    const float* h0 = (const float*)d_in[1];
    const float* c0 = (const float*)d_in[2];
    const float* emb = (const float*)d_in[3];
    const float* Wih = (const float*)d_in[4];
    const float* Whh = (const float*)d_in[5];
    const float* bih = (const float*)d_in[6];
    const float* bhh = (const float*)d_in[7];
    const float* Wout = (const float*)d_in[8];
    const float* bout = (const float*)d_in[9];
    float* out = (float*)d_out;

    float* gX;
    float* gGin;
    float* gHS;
    float* gP;
    cudaGetSymbolAddress((void**)&gX, g_X);
    cudaGetSymbolAddress((void**)&gGin, g_Gin);
    cudaGetSymbolAddress((void**)&gHS, g_HS);
    cudaGetSymbolAddress((void**)&gP, g_P);

    // 1) gather inputs + init tagged h0
    prep_kernel<<<65, 256>>>(sent, emb, h0);

    // 2) input projection, split-K=4: partials then combine (+ biases)
    {
        dim3 grid(4096 / 128, 4);
        gemm_splitk<<<grid, 128>>>(gX, Wih, gP, 4096, 1024, 4096, 4);
        dim3 cgrid(4096 / 256, 50);
        combine_gin_kernel<<<cgrid, 256>>>(bih, bhh);
    }

    // 3) persistent recurrence (register-resident W_hh, warp-per-unit)
    lstm_persistent<<<NBLK, 256>>>(Whh, gGin, c0);

    // 4) output projection, split-K=2: partials then combine (+ bias)
    {
        dim3 grid(LDP_OUT / 128, 2);
        gemm_splitk<<<grid, 128>>>(gHS, Wout, gP, NOUT, 1024, LDP_OUT, 2);
        dim3 cgrid((NOUT + 255) / 256, 50);
        combine_out_kernel<<<cgrid, 256>>>(bout, out);
    }
}

// round 7
// speedup vs baseline: 1.8459x; 1.8459x over previous
#include <cuda_runtime.h>
#include <cuda_bf16.h>
#include <math.h>

typedef unsigned long long ull;

#define NBLK 128
#define NSTEP 50
#define LDP_OUT 50304   // 393*128, padded ld for partials
#define NOUT 50257

// ---------------- device scratch (no allocs allowed) ----------------
__device__ float g_X[64 * 1024];          // padded inputs (rows 50..63 zero)
__device__ float g_Gin[50 * 4096];        // W_ih @ x_t + b_ih + b_hh
__device__ float g_HS[64 * 1024];         // h_t history (rows 50..63 zero)
__device__ float g_h[2][1024];            // double-buffered hidden state
__device__ unsigned g_arrive;             // cumulative grid-barrier counter
__device__ float g_P[2 * 64 * LDP_OUT];   // split-K partial buffers (reused)

// ---------------- helpers ----------------
__device__ __forceinline__ ull pack2(float x, float y) {
    ull r;
    asm("mov.b64 %0, {%1, %2};" : "=l"(r) : "f"(x), "f"(y));
    return r;
}
__device__ __forceinline__ void ffma2(ull& d, ull a, ull b) {
    asm("fma.rn.f32x2 %0, %1, %2, %0;" : "+l"(d) : "l"(a), "l"(b));
}
__device__ __forceinline__ float sum2(ull a) {
    float2 v = *(float2*)&a;
    return v.x + v.y;
}
__device__ __forceinline__ void red_release_add1(unsigned* p) {
    asm volatile("red.release.gpu.global.add.u32 [%0], 1;" :: "l"(p) : "memory");
}
__device__ __forceinline__ unsigned ld_acquire(const unsigned* p) {
    unsigned v;
    asm volatile("ld.acquire.gpu.global.u32 %0, [%1];" : "=r"(v) : "l"(p) : "memory");
    return v;
}

// ---------------- prep: gather X rows, zero pads, init state, reset barrier ----------------
__global__ void prep_kernel(const int* __restrict__ sent,
                            const float* __restrict__ emb,
                            const float* __restrict__ h0) {
    int b = blockIdx.x;
    int tid = threadIdx.x;  // 256 threads, float4 each -> 1024 floats
    if (b < 64) {
        float4* dst = (float4*)(g_X + b * 1024);
        if (b < 50) {
            int row = (b == 0) ? 1 : sent[b - 1];  // START_ID = 1
            const float4* src = (const float4*)(emb + (size_t)row * 1024);
            dst[tid] = src[tid];
        } else {
            float4 z = make_float4(0.f, 0.f, 0.f, 0.f);
            dst[tid] = z;
            ((float4*)(g_HS + b * 1024))[tid] = z;  // keep GEMM pad rows zero
        }
    } else {
        ((float4*)g_h[0])[tid] = ((const float4*)h0)[tid];
        if (tid == 0) g_arrive = 0u;
    }
}

// ---------------- split-K GEMM (R3-proven, unchanged) ----------------
// P[ks][m][n] = A[m][kbeg:kend] . W[n][kbeg:kend]
// BM=64, BN=128, BK=16, 128 threads, 8x8 thread tiles, f32x2, smem double-buffered.
__global__ __launch_bounds__(128) void gemm_splitk(
    const float* __restrict__ A, const float* __restrict__ W,
    float* __restrict__ P, int N, int K, int ldp, int nsplit) {
    __shared__ ull sAd[2][16][64];     // A duplicated as (a,a) pairs
    __shared__ float sB[2][16][128];

    const int tid = threadIdx.x;
    const int tn = tid & 15;   // n0 = tn*8
    const int tm = tid >> 4;   // m0 = tm*8
    const int n_block = blockIdx.x * 128;
    const int klen = K / nsplit;
    const int kbeg = blockIdx.y * klen;
    const int nk = klen / 16;
    float* Pp = P + (size_t)blockIdx.y * 64 * ldp;

    ull acc[8][4];
#pragma unroll
    for (int i = 0; i < 8; i++)
#pragma unroll
        for (int p = 0; p < 4; p++) acc[i][p] = 0ULL;

    const int mA = tid & 63;
    const int kgA = tid >> 6;
    const int nB = tid & 127;

    float4 ra[2], rb[4];
#pragma unroll
    for (int s = 0; s < 2; s++) {
        int kg = kgA + s * 2;
        ra[s] = *(const float4*)(A + (size_t)mA * K + kbeg + kg * 4);
    }
#pragma unroll
    for (int s = 0; s < 4; s++) {
        int gn = n_block + nB;
        rb[s] = make_float4(0.f, 0.f, 0.f, 0.f);
        if (gn < N) rb[s] = *(const float4*)(W + (size_t)gn * K + kbeg + s * 4);
    }
    {
#pragma unroll
        for (int s = 0; s < 2; s++) {
            int kg = kgA + s * 2;
            sAd[0][kg * 4 + 0][mA] = pack2(ra[s].x, ra[s].x);
            sAd[0][kg * 4 + 1][mA] = pack2(ra[s].y, ra[s].y);
            sAd[0][kg * 4 + 2][mA] = pack2(ra[s].z, ra[s].z);
            sAd[0][kg * 4 + 3][mA] = pack2(ra[s].w, ra[s].w);
        }
#pragma unroll
        for (int s = 0; s < 4; s++) {
            sB[0][s * 4 + 0][nB] = rb[s].x;
            sB[0][s * 4 + 1][nB] = rb[s].y;
            sB[0][s * 4 + 2][nB] = rb[s].z;
            sB[0][s * 4 + 3][nB] = rb[s].w;
        }
    }
    __syncthreads();

    for (int kt = 0; kt < nk; kt++) {
        const int buf = kt & 1;
        if (kt + 1 < nk) {
            int kp = kbeg + (kt + 1) * 16;
#pragma unroll
            for (int s = 0; s < 2; s++) {
                int kg = kgA + s * 2;
                ra[s] = *(const float4*)(A + (size_t)mA * K + kp + kg * 4);
            }
#pragma unroll
            for (int s = 0; s < 4; s++) {
                int gn = n_block + nB;
                rb[s] = make_float4(0.f, 0.f, 0.f, 0.f);
                if (gn < N) rb[s] = *(const float4*)(W + (size_t)gn * K + kp + s * 4);
            }
        }
#pragma unroll
        for (int k = 0; k < 16; k++) {
            const ull* ap = &sAd[buf][k][tm * 8];
            const ull* bp = (const ull*)&sB[buf][k][tn * 8];
            ull b0 = bp[0], b1 = bp[1], b2 = bp[2], b3 = bp[3];
#pragma unroll
            for (int i = 0; i < 8; i++) {
                ull ai = ap[i];
                ffma2(acc[i][0], ai, b0);
                ffma2(acc[i][1], ai, b1);
                ffma2(acc[i][2], ai, b2);
                ffma2(acc[i][3], ai, b3);
            }
        }
        if (kt + 1 < nk) {
            const int nb = buf ^ 1;
#pragma unroll
            for (int s = 0; s < 2; s++) {
                int kg = kgA + s * 2;
                sAd[nb][kg * 4 + 0][mA] = pack2(ra[s].x, ra[s].x);
                sAd[nb][kg * 4 + 1][mA] = pack2(ra[s].y, ra[s].y);
                sAd[nb][kg * 4 + 2][mA] = pack2(ra[s].z, ra[s].z);
                sAd[nb][kg * 4 + 3][mA] = pack2(ra[s].w, ra[s].w);
            }
#pragma unroll
            for (int s = 0; s < 4; s++) {
                sB[nb][s * 4 + 0][nB] = rb[s].x;
                sB[nb][s * 4 + 1][nB] = rb[s].y;
                sB[nb][s * 4 + 2][nB] = rb[s].z;
                sB[nb][s * 4 + 3][nB] = rb[s].w;
            }
            __syncthreads();
        }
    }

#pragma unroll
    for (int i = 0; i < 8; i++) {
        int m = tm * 8 + i;
        float4* dst = (float4*)(Pp + (size_t)m * ldp + n_block + tn * 8);
        dst[0] = *(float4*)&acc[i][0];
        dst[1] = *(float4*)&acc[i][2];
    }
}

// ---------------- combine: out = P0 + P1 + bias ----------------
__global__ void combine_out_kernel(const float* __restrict__ bout,
                                   float* __restrict__ out) {
    int m = blockIdx.y;
    int n = blockIdx.x * 256 + threadIdx.x;
    if (n < NOUT) {
        size_t po = (size_t)m * LDP_OUT + n;
        out[(size_t)m * NOUT + n] = g_P[po] + g_P[(size_t)64 * LDP_OUT + po] + bout[n];
    }
}

// ---------------- combine: Gin = P0+P1+P2+P3 + bih + bhh ----------------
__global__ void combine_gin_kernel(const float* __restrict__ bih,
                                   const float* __restrict__ bhh) {
    int m = blockIdx.y;
    int n = blockIdx.x * 256 + threadIdx.x;
    float s = bih[n] + bhh[n];
#pragma unroll
    for (int sp = 0; sp < 4; sp++) s += g_P[(size_t)sp * 64 * 4096 + (size_t)m * 4096 + n];
    g_Gin[(size_t)m * 4096 + n] = s;
}

// ---------------- persistent LSTM recurrence (R3 counter-barrier protocol) ----------------
// 128 blocks x 256 threads (1/SM). Block b owns units [b*8, b*8+8).
// Thread (w, r=lane>>3, c=lane&7): gate-row rid=w*4+r, cols {it*32 + c*4..+3}.
// Sync: coalesced publish by tid<8 -> __syncthreads -> tid0 red.release.gpu +
// acquire-spin on cumulative counter -> __syncthreads.  (Proven at 124.7us in R3;
// this round only removes work from the chain: packed W/h, smem Gin, fast-math tail.)
__global__ __launch_bounds__(256, 1) void lstm_persistent(
    const float* __restrict__ Whh,      // [4096][1024]
    const float* __restrict__ gin_all,  // [50][4096]
    const float* __restrict__ c0) {     // [1024]
    const int b = blockIdx.x;
    const int tid = threadIdx.x;
    const int w = tid >> 5;
    const int lane = tid & 31;
    const int r = lane >> 3;
    const int c = lane & 7;
    const int rid = w * 4 + r;           // 0..31
    const int gate = rid >> 3;           // 0..3
    const int jj = rid & 7;              // 0..7
    const int grow = gate * 1024 + b * 8 + jj;

    __shared__ __align__(16) ull h_q[512];  // h packed as (h2i, h2i+1) f32x2 pairs
    __shared__ float sg[32];
    __shared__ float c_s[8];
    __shared__ float sGin[NSTEP][4][8];     // this block's Gin slice, all steps

    // preload Gin slice: 200 segments of 8 floats (off the per-step chain)
    if (tid < 200) {
        int t = tid >> 2, g = tid & 3;
        const float4* src = (const float4*)(gin_all + (size_t)t * 4096 + g * 1024 + b * 8);
        ((float4*)&sGin[t][g][0])[0] = src[0];
        ((float4*)&sGin[t][g][0])[1] = src[1];
    }
    if (tid < 8) c_s[tid] = c0[b * 8 + tid];

    // W_hh slice into registers, pre-packed as f32x2 pairs (coalesced loads)
    ull Wq[64];
    const float4* wp = (const float4*)(Whh + (size_t)grow * 1024);
#pragma unroll
    for (int it = 0; it < 32; it++) {
        float4 w4 = wp[it * 8 + c];
        Wq[2 * it + 0] = pack2(w4.x, w4.y);
        Wq[2 * it + 1] = pack2(w4.z, w4.w);
    }
    __syncthreads();

    for (int t = 0; t < NSTEP; t++) {
        // stage h packed (prior barrier guarantees visibility)
        {
            float4 hv = ((const float4*)g_h[t & 1])[tid];
            ulonglong2 hq;
            hq.x = pack2(hv.x, hv.y);
            hq.y = pack2(hv.z, hv.w);
            *((ulonglong2*)&h_q[2 * tid]) = hq;
        }
        __syncthreads();

        ull a0 = 0, a1 = 0;
#pragma unroll
        for (int it = 0; it < 32; it++) {
            ulonglong2 hq = *(const ulonglong2*)&h_q[it * 16 + c * 2];  // bcast, conflict-free
            ffma2(a0, Wq[2 * it + 0], hq.x);
            ffma2(a1, Wq[2 * it + 1], hq.y);
        }
        float sum = sum2(a0) + sum2(a1);
        sum += __shfl_xor_sync(0xFFFFFFFFu, sum, 1);
        sum += __shfl_xor_sync(0xFFFFFFFFu, sum, 2);
        sum += __shfl_xor_sync(0xFFFFFFFFu, sum, 4);
        if (c == 0) sg[rid] = sum;
        __syncthreads();

        if (tid < 8) {
            const int j = tid;
            float vi = sg[0 * 8 + j] + sGin[t][0][j];
            float vf = sg[1 * 8 + j] + sGin[t][1][j];
            float vg = sg[2 * 8 + j] + sGin[t][2][j];
            float vo = sg[3 * 8 + j] + sGin[t][3][j];
            float ig = __fdividef(1.f, 1.f + __expf(-vi));
            float fg = __fdividef(1.f, 1.f + __expf(-vf));
            float gg = 1.f - __fdividef(2.f, __expf(2.f * vg) + 1.f);
            float og = __fdividef(1.f, 1.f + __expf(-vo));
            float cn = fg * c_s[j] + ig * gg;
            c_s[j] = cn;
            float hn = og * (1.f - __fdividef(2.f, __expf(2.f * cn) + 1.f));
            g_h[(t + 1) & 1][b * 8 + j] = hn;   // coalesced warp-0 publish
            g_HS[(size_t)t * 1024 + b * 8 + j] = hn;
        }
        __syncthreads();  // block writes ordered before the release below

        if (tid == 0) {
            red_release_add1(&g_arrive);  // release publishes block's writes
            const unsigned target = (unsigned)NBLK * (unsigned)(t + 1);
            while (ld_acquire(&g_arrive) < target) {}
        }
        __syncthreads();
    }
}

// ---------------- launch ----------------
extern "C" void kernel_launch(void* const* d_in, const int* in_sizes, int n_in,
                              void* d_out, int out_size) {
    const int* sent = (const int*)d_in[0];
    const float* h0 = (const float*)d_in[1];
    const float* c0 = (const float*)d_in[2];
    const float* emb = (const float*)d_in[3];
    const float* Wih = (const float*)d_in[4];
    const float* Whh = (const float*)d_in[5];
    const float* bih = (const float*)d_in[6];
    const float* bhh = (const float*)d_in[7];
    const float* Wout = (const float*)d_in[8];
    const float* bout = (const float*)d_in[9];
    float* out = (float*)d_out;

    float* gX;
    float* gGin;
    float* gHS;
    float* gP;
    cudaGetSymbolAddress((void**)&gX, g_X);
    cudaGetSymbolAddress((void**)&gGin, g_Gin);
    cudaGetSymbolAddress((void**)&gHS, g_HS);
    cudaGetSymbolAddress((void**)&gP, g_P);

    // 1) gather inputs + init state + reset barrier
    prep_kernel<<<65, 256>>>(sent, emb, h0);

    // 2) input projection, split-K=4: partials then combine (+ biases)
    {
        dim3 grid(4096 / 128, 4);
        gemm_splitk<<<grid, 128>>>(gX, Wih, gP, 4096, 1024, 4096, 4);
        dim3 cgrid(4096 / 256, 50);
        combine_gin_kernel<<<cgrid, 256>>>(bih, bhh);
    }

    // 3) persistent recurrence (register-resident W_hh, counter barrier)
    lstm_persistent<<<NBLK, 256>>>(Whh, gGin, c0);

    // 4) output projection, split-K=2: partials then combine (+ bias)
    {
        dim3 grid(LDP_OUT / 128, 2);
        gemm_splitk<<<grid, 128>>>(gHS, Wout, gP, NOUT, 1024, LDP_OUT, 2);
        dim3 cgrid((NOUT + 255) / 256, 50);
        combine_out_kernel<<<cgrid, 256>>>(bout, out);
    }
}